// round 6
// baseline (speedup 1.0000x reference)
#include <cuda_runtime.h>

// Problem constants
#define IN_F    2048
#define OUT_F   4096
#define BATCHN  131072
#define IN_F4   (IN_F / 4)        // 512 float4 columns

#define NSLICE  256               // 4096 rows / 16 rows per slice

// Scratch globals (allocation-free). Fully rewritten every launch =>
// graph-replay deterministic.
__device__ float4 g_partial4[NSLICE * IN_F4];   // 2 MiB partial column sums
__device__ float  g_wsum[IN_F];
__device__ float  g_bsum;

// ---------------------------------------------------------------------------
// Kernel 1: partial column-sums of weight.
// grid = (2, 256), block = 256. Block (bx, by): rows [by*16, by*16+16),
// float4-columns [bx*256, bx*256+256).
// Explicit float4 t[16] batch forces 16 independent LDG.128 in flight per
// thread BEFORE any consume (defeats ptxas chain-collapsing seen in R3 where
// regs=31 => MLP~6 => 3.4 TB/s). 512 blocks ≈ 3.5/SM ≈ 28 warps/SM.
// ---------------------------------------------------------------------------
__global__ __launch_bounds__(256) void reduce_weight_kernel(const float4* __restrict__ w) {
    const int c  = blockIdx.x * 256 + threadIdx.x;   // float4 column
    const int r0 = blockIdx.y * 16;                  // first row of slice
    const float4* wp = w + (size_t)r0 * IN_F4 + c;

    float4 t[16];
    #pragma unroll
    for (int i = 0; i < 16; ++i) {
        t[i] = wp[(size_t)i * IN_F4];
    }

    // Pairwise tree sum (independent adds, short chain).
    #pragma unroll
    for (int stride = 8; stride > 0; stride >>= 1) {
        #pragma unroll
        for (int i = 0; i < 16; ++i) {
            if (i < stride) {
                t[i].x += t[i + stride].x;
                t[i].y += t[i + stride].y;
                t[i].z += t[i + stride].z;
                t[i].w += t[i + stride].w;
            }
        }
    }
    g_partial4[blockIdx.y * IN_F4 + c] = t[0];
}

// ---------------------------------------------------------------------------
// Kernel 2: fold NSLICE partials -> w_sum; block 2 reduces bias -> b_sum.
// grid = 3, block = 256. Fixed-order => deterministic. Partials L2-resident.
// ---------------------------------------------------------------------------
__global__ __launch_bounds__(256) void finalize_kernel(const float* __restrict__ bias) {
    if (blockIdx.x < 2) {
        const int c = blockIdx.x * 256 + threadIdx.x;   // float4 column
        float4 s0 = make_float4(0.f, 0.f, 0.f, 0.f);
        float4 s1 = make_float4(0.f, 0.f, 0.f, 0.f);
        float4 s2 = make_float4(0.f, 0.f, 0.f, 0.f);
        float4 s3 = make_float4(0.f, 0.f, 0.f, 0.f);
        #pragma unroll 8
        for (int p = 0; p < NSLICE; p += 4) {
            const float4 a = g_partial4[(p + 0) * IN_F4 + c];
            const float4 b = g_partial4[(p + 1) * IN_F4 + c];
            const float4 d = g_partial4[(p + 2) * IN_F4 + c];
            const float4 e = g_partial4[(p + 3) * IN_F4 + c];
            s0.x += a.x; s0.y += a.y; s0.z += a.z; s0.w += a.w;
            s1.x += b.x; s1.y += b.y; s1.z += b.z; s1.w += b.w;
            s2.x += d.x; s2.y += d.y; s2.z += d.z; s2.w += d.w;
            s3.x += e.x; s3.y += e.y; s3.z += e.z; s3.w += e.w;
        }
        s0.x += s1.x; s0.y += s1.y; s0.z += s1.z; s0.w += s1.w;
        s2.x += s3.x; s2.y += s3.y; s2.z += s3.z; s2.w += s3.w;
        s0.x += s2.x; s0.y += s2.y; s0.z += s2.z; s0.w += s2.w;
        reinterpret_cast<float4*>(g_wsum)[c] = s0;
    } else {
        // bias reduction: 4096 elements, deterministic tree.
        __shared__ float red[256];
        float s = 0.0f;
        #pragma unroll
        for (int i = 0; i < OUT_F / 256; ++i) {
            s += bias[i * 256 + threadIdx.x];
        }
        red[threadIdx.x] = s;
        __syncthreads();
        #pragma unroll
        for (int stride = 128; stride > 0; stride >>= 1) {
            if (threadIdx.x < stride) red[threadIdx.x] += red[threadIdx.x + stride];
            __syncthreads();
        }
        if (threadIdx.x == 0) g_bsum = red[0];
    }
}

// ---------------------------------------------------------------------------
// Kernel 3: out[row] = dot(x[row,:], w_sum) + b_sum.
// EXACTLY the R1 kernel (measured 7.35 TB/s standalone). Do not touch.
// Warp-per-row. block = 256 (8 warps), grid = BATCH/8 = 16384.
// ---------------------------------------------------------------------------
__global__ __launch_bounds__(256) void gemv_kernel(const float* __restrict__ x,
                                                   float* __restrict__ out) {
    __shared__ float4 sw[IN_F4];   // 8 KB
    __shared__ float sb;

    const int tid = threadIdx.x;
    #pragma unroll
    for (int i = 0; i < IN_F4 / 256; ++i) {
        sw[i * 256 + tid] = reinterpret_cast<const float4*>(g_wsum)[i * 256 + tid];
    }
    if (tid == 0) sb = g_bsum;
    __syncthreads();

    const int warp = tid >> 5;
    const int lane = tid & 31;
    const int row  = blockIdx.x * 8 + warp;

    const float4* xr = reinterpret_cast<const float4*>(x + (size_t)row * IN_F);

    float acc = 0.0f;
    #pragma unroll
    for (int i = 0; i < 16; ++i) {          // 16 * 32 lanes * 4 floats = 2048
        const float4 xv = xr[i * 32 + lane];
        const float4 wv = sw[i * 32 + lane];
        acc += xv.x * wv.x + xv.y * wv.y + xv.z * wv.z + xv.w * wv.w;
    }

    #pragma unroll
    for (int off = 16; off > 0; off >>= 1) {
        acc += __shfl_xor_sync(0xFFFFFFFFu, acc, off);
    }
    if (lane == 0) {
        out[row] = acc + sb;
    }
}

// ---------------------------------------------------------------------------
extern "C" void kernel_launch(void* const* d_in, const int* in_sizes, int n_in,
                              void* d_out, int out_size) {
    const float* x      = (const float*)d_in[0];  // (131072, 2048)
    const float* weight = (const float*)d_in[1];  // (4096, 2048)
    const float* bias   = (const float*)d_in[2];  // (4096,)
    float* out = (float*)d_out;                   // (131072, 1)

    (void)in_sizes; (void)n_in; (void)out_size;

    dim3 g1(2, NSLICE);
    reduce_weight_kernel<<<g1, 256>>>(reinterpret_cast<const float4*>(weight));
    finalize_kernel<<<3, 256>>>(bias);
    gemv_kernel<<<BATCHN / 8, 256>>>(x, out);
}

// round 8
// speedup vs baseline: 1.1175x; 1.1175x over previous
#include <cuda_runtime.h>

// Problem constants
#define IN_F    2048
#define OUT_F   4096
#define BATCHN  131072
#define IN_F4   (IN_F / 4)        // 512 float4 columns

// Fused-kernel block layout (bid order gives deadlock-freedom: every
// spin-free producer bid < every spinning consumer bid that waits on it,
// and low bids are wave-1 resident deterministically).
#define NFOLD    16               // folder blocks (bids 0..15)
#define BID_BIAS 16
#define NRED     512              // weight reducers (bids 17..528), 16 rows each
#define BID_RED0 17
#define BID_GEMV0 (BID_RED0 + NRED)          // 529
#define NGEMV    (BATCHN / 8)                // 16384
#define GRID_TOTAL (BID_GEMV0 + NGEMV)       // 16913

#define NSLICE   256              // 4096 rows / 16 rows per reducer slice

// Scratch globals (allocation-free, fully rewritten every launch =>
// graph-replay deterministic).
__device__ float4 g_partial4[NSLICE * IN_F4];   // 2 MiB
__device__ float  g_wsum[IN_F];
__device__ float  g_bsum;
__device__ int    g_red_done;     // -> NRED
__device__ int    g_fold_done;    // -> NFOLD + 1

__global__ void init_kernel() {
    g_red_done  = 0;
    g_fold_done = 0;
}

// ---------------------------------------------------------------------------
__global__ __launch_bounds__(256) void fused_kernel(const float4* __restrict__ w4,
                                                    const float*  __restrict__ x,
                                                    const float*  __restrict__ bias,
                                                    float* __restrict__ out) {
    __shared__ float4 sw[IN_F4];      // 8 KB
    const int tid = threadIdx.x;
    const int bid = blockIdx.x;

    // ======================== GEMV blocks (hot path) ========================
    if (bid >= BID_GEMV0) {
        const int gvb  = bid - BID_GEMV0;
        const int warp = tid >> 5;
        const int lane = tid & 31;
        const int row  = gvb * 8 + warp;
        const float4* xr = reinterpret_cast<const float4*>(x + (size_t)row * IN_F);

        // Issue first half of this thread's REAL x loads before waiting.
        // Register-destined, single-use: they overlap the weight-reduction
        // phase without polluting L2 (unlike the R4 prefetch burst).
        float4 xa[8];
        #pragma unroll
        for (int i = 0; i < 8; ++i) {
            xa[i] = xr[i * 32 + lane];
        }

        // Wait for w_sum + b_sum (loads above stay in flight).
        if (tid == 0) {
            int backoff = 32;
            while (*(volatile int*)&g_fold_done != (NFOLD + 1)) {
                __nanosleep(backoff);
                if (backoff < 1024) backoff <<= 1;
            }
            __threadfence();
        }
        __syncthreads();

        // Stage w_sum into shared.
        #pragma unroll
        for (int i = 0; i < IN_F4 / 256; ++i) {
            sw[i * 256 + tid] = reinterpret_cast<const float4*>(g_wsum)[i * 256 + tid];
        }
        __syncthreads();
        const float bsum = g_bsum;

        float acc = 0.0f;
        #pragma unroll
        for (int i = 0; i < 8; ++i) {           // preloaded half
            const float4 wv = sw[i * 32 + lane];
            acc += xa[i].x * wv.x + xa[i].y * wv.y + xa[i].z * wv.z + xa[i].w * wv.w;
        }
        #pragma unroll
        for (int i = 8; i < 16; ++i) {          // streamed half
            const float4 xv = xr[i * 32 + lane];
            const float4 wv = sw[i * 32 + lane];
            acc += xv.x * wv.x + xv.y * wv.y + xv.z * wv.z + xv.w * wv.w;
        }
        #pragma unroll
        for (int off = 16; off > 0; off >>= 1) {
            acc += __shfl_xor_sync(0xFFFFFFFFu, acc, off);
        }
        if (lane == 0) out[row] = acc + bsum;
        return;
    }

    // ======================== Weight reducer blocks ========================
    if (bid >= BID_RED0) {
        const int r  = bid - BID_RED0;
        const int cg = r & 1;              // column group
        const int s  = r >> 1;             // 16-row slice
        const int c  = cg * 256 + tid;
        const float4* wp = w4 + (size_t)(s * 16) * IN_F4 + c;

        float4 acc = make_float4(0.f, 0.f, 0.f, 0.f);
        #pragma unroll
        for (int b = 0; b < 2; ++b) {
            float4 t[8];
            #pragma unroll
            for (int i = 0; i < 8; ++i) t[i] = wp[(size_t)(b * 8 + i) * IN_F4];
            #pragma unroll
            for (int i = 0; i < 8; ++i) {
                acc.x += t[i].x; acc.y += t[i].y; acc.z += t[i].z; acc.w += t[i].w;
            }
        }
        g_partial4[s * IN_F4 + c] = acc;
        __threadfence();
        __syncthreads();
        if (tid == 0) atomicAdd(&g_red_done, 1);
        return;
    }

    // ======================== Bias block ========================
    if (bid == BID_BIAS) {
        __shared__ float red[256];
        float s = 0.0f;
        #pragma unroll
        for (int i = 0; i < OUT_F / 256; ++i) s += bias[i * 256 + tid];
        red[tid] = s;
        __syncthreads();
        #pragma unroll
        for (int stride = 128; stride > 0; stride >>= 1) {
            if (tid < stride) red[tid] += red[tid + stride];
            __syncthreads();
        }
        if (tid == 0) {
            g_bsum = red[0];
            __threadfence();
            atomicAdd(&g_fold_done, 1);
        }
        return;
    }

    // ======================== Folder blocks (bids 0..15) ========================
    {
        if (tid == 0) {
            int backoff = 32;
            while (*(volatile int*)&g_red_done != NRED) {
                __nanosleep(backoff);
                if (backoff < 1024) backoff <<= 1;
            }
            __threadfence();
        }
        __syncthreads();

        const int lane = tid & 31;
        const int wrp  = tid >> 5;           // 8 warps = 8 slice groups
        const int col  = bid * 32 + lane;    // this block's 32 float4 columns

        float4 acc = make_float4(0.f, 0.f, 0.f, 0.f);
        #pragma unroll 8
        for (int j = 0; j < 32; ++j) {       // slices p = wrp + 8*j
            const float4 v = g_partial4[(wrp + 8 * j) * IN_F4 + col];
            acc.x += v.x; acc.y += v.y; acc.z += v.z; acc.w += v.w;
        }

        float4* sh = sw;                     // 8*32 float4 = 4 KB
        sh[wrp * 32 + lane] = acc;
        __syncthreads();
        if (wrp == 0) {
            float4 t = sh[lane];
            #pragma unroll
            for (int p = 1; p < 8; ++p) {
                const float4 v = sh[p * 32 + lane];
                t.x += v.x; t.y += v.y; t.z += v.z; t.w += v.w;
            }
            reinterpret_cast<float4*>(g_wsum)[col] = t;
            __threadfence();
        }
        __syncthreads();
        if (tid == 0) atomicAdd(&g_fold_done, 1);
        return;
    }
}

// ---------------------------------------------------------------------------
extern "C" void kernel_launch(void* const* d_in, const int* in_sizes, int n_in,
                              void* d_out, int out_size) {
    const float* x      = (const float*)d_in[0];  // (131072, 2048)
    const float* weight = (const float*)d_in[1];  // (4096, 2048)
    const float* bias   = (const float*)d_in[2];  // (4096,)
    float* out = (float*)d_out;                   // (131072, 1)

    (void)in_sizes; (void)n_in; (void)out_size;

    init_kernel<<<1, 1>>>();
    fused_kernel<<<GRID_TOTAL, 256>>>(reinterpret_cast<const float4*>(weight),
                                      x, bias, out);
}